// round 3
// baseline (speedup 1.0000x reference)
#include <cuda_runtime.h>
#include <math.h>

#define HH 1024
#define WW 1024
#define NB 2
#define KK 24   // number of SOCS kernels
#define KD 35   // kernel spatial size / cropped spectrum size (NOT 24!)
#define FC 17   // center offset: frequency f = index - 17

// ---------------- scratch (static __device__, no allocation) ----------------
__device__ float2 g_cs[1024];                 // e^{+2pi i t/1024}
__device__ float2 g_T[NB][HH][KD];            // row DFT of mask: (n, y, j2)
__device__ float2 g_spec[NB][KD][KD];         // cropped spectrum (1/(H*W) folded)
__device__ float2 g_B[NB][2][KK][KD][KD];     // spec * kernel
__device__ float2 g_R[NB][2][KK][KD][WW];     // row-synthesized fields
__device__ float2 g_Dpart[8][NB][2][KD][WW];  // per-k-group partial Gram
__device__ float2 g_D[NB][2][KD][WW];         // cross-spectral density over du

// ---------------- twiddle table ----------------
__global__ void k_table() {
    int t = threadIdx.x;
    float s, c;
    sincospif((float)t / 512.0f, &s, &c);     // angle = 2*pi*t/1024
    g_cs[t] = make_float2(c, s);
}

// ---------------- stage 1: avepool3 + sigmoid + row DFT (35 freqs) ----------------
__global__ void __launch_bounds__(768) k_rowdft(const float* __restrict__ mask) {
    __shared__ float rows[3][WW];
    __shared__ float colsum[WW];
    __shared__ float m[WW];
    __shared__ float2 cs[WW];
    int y = blockIdx.x;
    int n = blockIdx.y;
    int tid = threadIdx.x;
    const float* base = mask + (size_t)n * HH * WW;
    for (int x = tid; x < WW; x += blockDim.x) {
        rows[0][x] = (y > 0)      ? base[(size_t)(y-1)*WW + x] : 0.f;
        rows[1][x] =                base[(size_t)y*WW + x];
        rows[2][x] = (y < HH-1)   ? base[(size_t)(y+1)*WW + x] : 0.f;
        cs[x] = g_cs[x];
    }
    __syncthreads();
    for (int x = tid; x < WW; x += blockDim.x)
        colsum[x] = rows[0][x] + rows[1][x] + rows[2][x];
    __syncthreads();
    for (int x = tid; x < WW; x += blockDim.x) {
        float s = colsum[x];
        if (x > 0)    s += colsum[x-1];
        if (x < WW-1) s += colsum[x+1];
        float p = s * (1.0f/9.0f);                    // zero-padded 3x3 average
        m[x] = 1.0f / (1.0f + expf(-4.0f * (p - 0.5f)));
    }
    __syncthreads();
    int warp = tid >> 5, lane = tid & 31;             // 24 warps
    for (int j2 = warp; j2 < KD; j2 += 24) {
        // spec col j2 -> frequency f2 = j2-17; e^{-2pi i f2 x/N} = cs[((17-j2)*x) mod N]
        int a = FC - j2;
        float ar = 0.f, ai = 0.f;
        #pragma unroll 4
        for (int i = 0; i < WW/32; i++) {
            int x = lane + 32*i;
            float mv = m[x];
            float2 t = cs[(a * x) & (WW-1)];
            ar += mv * t.x;
            ai += mv * t.y;
        }
        for (int o = 16; o; o >>= 1) {
            ar += __shfl_xor_sync(0xffffffffu, ar, o);
            ai += __shfl_xor_sync(0xffffffffu, ai, o);
        }
        if (lane == 0) g_T[n][y][j2] = make_float2(ar, ai);
    }
}

// ---------------- stage 2: column DFT -> 35x35 spec (1/(H*W) folded once) ----------------
__global__ void __launch_bounds__(128) k_coldft() {
    int j1 = blockIdx.x, j2 = blockIdx.y, n = blockIdx.z;
    int tid = threadIdx.x;
    int a = FC - j1;
    float ar = 0.f, ai = 0.f;
    for (int y = tid; y < HH; y += 128) {
        float2 T = g_T[n][y][j2];
        float2 t = g_cs[(a * y) & (HH-1)];
        ar += T.x*t.x - T.y*t.y;
        ai += T.x*t.y + T.y*t.x;
    }
    for (int o = 16; o; o >>= 1) {
        ar += __shfl_xor_sync(0xffffffffu, ar, o);
        ai += __shfl_xor_sync(0xffffffffu, ai, o);
    }
    __shared__ float2 part[4];
    int warp = tid >> 5, lane = tid & 31;
    if (lane == 0) part[warp] = make_float2(ar, ai);
    __syncthreads();
    if (tid == 0) {
        float sr = 0.f, si = 0.f;
        #pragma unroll
        for (int wq = 0; wq < 4; wq++) { sr += part[wq].x; si += part[wq].y; }
        const float norm = 1.0f / (1024.0f * 1024.0f);
        g_spec[n][j1][j2] = make_float2(sr * norm, si * norm);
    }
}

// ---------------- stage 3: B = spec * kernel ----------------
__global__ void __launch_bounds__(1024) k_B(const float* __restrict__ fr, const float* __restrict__ fi,
                                            const float* __restrict__ dr, const float* __restrict__ di) {
    int k = blockIdx.x, br = blockIdx.y, n = blockIdx.z;
    const float* krp = (br == 0) ? fr : dr;
    const float* kip = (br == 0) ? fi : di;
    for (int t = threadIdx.x; t < KD*KD; t += 1024) {
        int u = t / KD, v = t % KD;
        float2 A = g_spec[n][u][v];
        float Kr = krp[(k*KD + u)*KD + v];
        float Ki = kip[(k*KD + u)*KD + v];
        g_B[n][br][k][u][v] = make_float2(A.x*Kr - A.y*Ki, A.x*Ki + A.y*Kr);
    }
}

// ---------------- stage 4: R[k,u,x] = sum_v B[k,u,v] * e^{+2pi i v x / 1024} ----------------
__global__ void __launch_bounds__(256) k_R() {
    int xt  = blockIdx.x;                    // 4 tiles of 256 x
    int k   = blockIdx.y;
    int nbr = blockIdx.z; int n = nbr >> 1, br = nbr & 1;
    int tid = threadIdx.x;
    __shared__ float2 Bs[KD][KD];
    __shared__ float2 cs[1024];
    for (int i = tid; i < KD*KD; i += 256)
        (&Bs[0][0])[i] = (&g_B[n][br][k][0][0])[i];
    for (int i = tid; i < 1024; i += 256)
        cs[i] = g_cs[i];
    __syncthreads();
    int x = xt*256 + tid;
    float2 p[KD];
    #pragma unroll
    for (int v = 0; v < KD; v++)
        p[v] = cs[(v * x) & 1023];           // exact table twiddles
    for (int u = 0; u < KD; u++) {
        float ar = 0.f, ai = 0.f;
        #pragma unroll
        for (int v = 0; v < KD; v++) {
            float2 b = Bs[u][v];
            ar += b.x*p[v].x - b.y*p[v].y;
            ai += b.x*p[v].y + b.y*p[v].x;
        }
        g_R[n][br][k][u][x] = make_float2(ar, ai);
    }
}

// ---------------- stage 5a: partial Gram ----------------
// Dpart[kg][du,x] = sum_{k in group} s_k * sum_u R[k,u,x]*conj(R[k,u-du,x])
// du split into two halves across gridDim.z to bound register pressure.
template <int DU0, int DW>
__device__ __forceinline__ void gram_half(int n, int br, int kg, int x, const float* sp) {
    float2 acc[DW];
    #pragma unroll
    for (int j = 0; j < DW; j++) acc[j] = make_float2(0.f, 0.f);
    for (int kk = 0; kk < 3; kk++) {
        int k = kg*3 + kk;
        float s = sp[k];
        float2 Ru[KD];
        #pragma unroll
        for (int u = 0; u < KD; u++) Ru[u] = g_R[n][br][k][u][x];
        #pragma unroll
        for (int u = 0; u < KD; u++) {
            float ax = s * Ru[u].x;
            float ay = s * Ru[u].y;
            #pragma unroll
            for (int j = 0; j < DW; j++) {
                if (DU0 + j <= u) {
                    float2 b = Ru[u - DU0 - j];      // s * R[u] * conj(R[u-du])
                    acc[j].x += ax*b.x + ay*b.y;
                    acc[j].y += ay*b.x - ax*b.y;
                }
            }
        }
    }
    #pragma unroll
    for (int j = 0; j < DW; j++)
        g_Dpart[kg][n][br][DU0 + j][x] = acc[j];
}

__global__ void __launch_bounds__(128) k_D1(const float* __restrict__ fs, const float* __restrict__ ds) {
    int xt  = blockIdx.x;                    // 8 tiles of 128 x
    int kg  = blockIdx.y;                    // 8 k-groups of 3
    int z   = blockIdx.z;                    // nbr(4) * half(2)
    int nbr = z >> 1, half = z & 1;
    int n = nbr >> 1, br = nbr & 1;
    int x = xt*128 + threadIdx.x;
    const float* sp = (br == 0) ? fs : ds;
    if (half == 0) gram_half<0, 18>(n, br, kg, x, sp);
    else           gram_half<18, 17>(n, br, kg, x, sp);
}

// ---------------- stage 5b: reduce k-group partials ----------------
__global__ void __launch_bounds__(1024) k_D2() {
    int du = blockIdx.x, nbr = blockIdx.y; int n = nbr >> 1, br = nbr & 1;
    int x = threadIdx.x;
    float sx = 0.f, sy = 0.f;
    #pragma unroll
    for (int kg = 0; kg < 8; kg++) {
        float2 t = g_Dpart[kg][n][br][du][x];
        sx += t.x; sy += t.y;
    }
    g_D[n][br][du][x] = make_float2(sx, sy);
}

// ---------------- stage 6: synthesis + outputs ----------------
// I(y,x) = D[0,x].re + 2 * sum_{du=1..34} Re(D[du,x] * e^{+2pi i du y/1024})
__global__ void __launch_bounds__(256) k_finalF(float* __restrict__ out) {
    __shared__ float2 cs[1024];
    int xs = blockIdx.x;                     // 32-wide x strip
    int yq = blockIdx.y;                     // 0..3 (256 rows each)
    int n  = blockIdx.z;
    int tid = threadIdx.x;
    for (int i = tid; i < 1024; i += 256) cs[i] = g_cs[i];
    int lane = tid & 31, warp = tid >> 5;    // 8 warps
    int x = xs*32 + lane;

    float D0 = g_D[n][0][0][x].x;            // D[0] is real
    float2 Dc[KD-1];
    #pragma unroll
    for (int du = 1; du < KD; du++) {
        float2 t = g_D[n][0][du][x];
        Dc[du-1] = make_float2(2.f*t.x, 2.f*t.y);
    }
    __syncthreads();

    const size_t plane = (size_t)NB * HH * WW;
    const size_t base  = (size_t)n * HH * WW;
    for (int yy = 0; yy < 32; yy++) {
        int y = yq*256 + warp*32 + yy;
        float I = D0;
        #pragma unroll
        for (int du = 1; du < KD; du++) {
            float2 t = cs[(du * y) & 1023];  // warp-uniform -> broadcast LDS
            I += Dc[du-1].x * t.x - Dc[du-1].y * t.y;
        }
        float Imax = 1.0404f * I;            // dose 1.02^2
        size_t o = base + (size_t)y * WW + x;
        out[o]             = 1.f/(1.f + expf(-50.f*(I    - 0.225f)));   // nominal
        out[2*plane + o]   = 1.f/(1.f + expf(-50.f*(Imax - 0.225f)));   // outer
        out[3*plane + o]   = I;                                         // x_out
        out[5*plane + o]   = Imax;                                      // x_out_max
    }
}

__global__ void __launch_bounds__(256) k_finalD(float* __restrict__ out) {
    __shared__ float2 cs[1024];
    int xs = blockIdx.x;
    int yq = blockIdx.y;
    int n  = blockIdx.z;
    int tid = threadIdx.x;
    for (int i = tid; i < 1024; i += 256) cs[i] = g_cs[i];
    int lane = tid & 31, warp = tid >> 5;
    int x = xs*32 + lane;

    float D0 = g_D[n][1][0][x].x;
    float2 Dc[KD-1];
    #pragma unroll
    for (int du = 1; du < KD; du++) {
        float2 t = g_D[n][1][du][x];
        Dc[du-1] = make_float2(2.f*t.x, 2.f*t.y);
    }
    __syncthreads();

    const size_t plane = (size_t)NB * HH * WW;
    const size_t base  = (size_t)n * HH * WW;
    for (int yy = 0; yy < 32; yy++) {
        int y = yq*256 + warp*32 + yy;
        float I = D0;
        #pragma unroll
        for (int du = 1; du < KD; du++) {
            float2 t = cs[(du * y) & 1023];
            I += Dc[du-1].x * t.x - Dc[du-1].y * t.y;
        }
        float Imin = 0.9604f * I;            // dose 0.98^2
        size_t o = base + (size_t)y * WW + x;
        out[plane   + o]   = 1.f/(1.f + expf(-50.f*(Imin - 0.225f)));   // inner
        out[4*plane + o]   = Imin;                                      // x_out_min
    }
}

// ---------------- launch ----------------
extern "C" void kernel_launch(void* const* d_in, const int* in_sizes, int n_in,
                              void* d_out, int out_size) {
    const float* mask = (const float*)d_in[0];
    const float* fr   = (const float*)d_in[1];
    const float* fi   = (const float*)d_in[2];
    const float* dr   = (const float*)d_in[3];
    const float* di   = (const float*)d_in[4];
    const float* fs   = (const float*)d_in[5];
    const float* ds   = (const float*)d_in[6];
    float* out = (float*)d_out;

    k_table  <<<1, 1024>>>();
    k_rowdft <<<dim3(1024, 2), 768>>>(mask);
    k_coldft <<<dim3(KD, KD, 2), 128>>>();
    k_B      <<<dim3(KK, 2, 2), 1024>>>(fr, fi, dr, di);
    k_R      <<<dim3(4, KK, 4), 256>>>();
    k_D1     <<<dim3(8, 8, 8), 128>>>(fs, ds);
    k_D2     <<<dim3(KD, 4), 1024>>>();
    k_finalF <<<dim3(32, 4, 2), 256>>>(out);
    k_finalD <<<dim3(32, 4, 2), 256>>>(out);
}

// round 4
// speedup vs baseline: 1.4719x; 1.4719x over previous
#include <cuda_runtime.h>
#include <math.h>

#define HH 1024
#define WW 1024
#define NB 2
#define KK 24   // number of SOCS kernels
#define KD 35   // kernel spatial size / cropped spectrum size
#define FC 17   // center offset: frequency f = index - 17
#define U2 18   // ceil(KD/2) u-pairs (pair 17 has a zero upper half)
#define U2P 20  // padded row length for 16B-aligned LDS.128

// ---------------- scratch (static __device__, no allocation) ----------------
__device__ float2 g_cs[1024];                 // e^{+2pi i t/1024}
__device__ float  g_m[NB][HH][WW];            // pooled+sigmoid mask
__device__ float2 g_T[NB][KD][HH];            // row DFT, TRANSPOSED (j2-major)
__device__ float2 g_spec[NB][KD][KD];         // cropped spectrum (1/(H*W) folded)
__device__ float2 g_R[NB][2][KK][KD][WW];     // row-synthesized fields
__device__ float2 g_Dpart[8][NB][2][KD][WW];  // per-k-group partial Gram
__device__ float2 g_D[NB][2][KD][WW];         // cross-spectral density over du

// ---------------- f32x2 packed helpers (Blackwell) ----------------
__device__ __forceinline__ unsigned long long pk2(float lo, float hi) {
    unsigned long long r;
    asm("mov.b64 %0, {%1, %2};" : "=l"(r) : "f"(lo), "f"(hi));
    return r;
}
__device__ __forceinline__ unsigned long long fma2(unsigned long long a, unsigned long long b, unsigned long long c) {
    unsigned long long d;
    asm("fma.rn.f32x2 %0, %1, %2, %3;" : "=l"(d) : "l"(a), "l"(b), "l"(c));
    return d;
}
__device__ __forceinline__ void upk2(unsigned long long v, float& lo, float& hi) {
    asm("mov.b64 {%0, %1}, %2;" : "=f"(lo), "=f"(hi) : "l"(v));
}

// ---------------- twiddle table ----------------
__global__ void k_table() {
    int t = threadIdx.x;
    float s, c;
    sincospif((float)t / 512.0f, &s, &c);     // angle = 2*pi*t/1024
    g_cs[t] = make_float2(c, s);
}

// ---------------- stage 0: avepool3 + sigmoid -> g_m ----------------
__global__ void __launch_bounds__(256) k_mask(const float* __restrict__ mask) {
    __shared__ float colsum[WW];
    int y = blockIdx.x;
    int n = blockIdx.y;
    int tid = threadIdx.x;
    const float* base = mask + (size_t)n * HH * WW;
    for (int x = tid; x < WW; x += 256) {
        float s = base[(size_t)y * WW + x];
        if (y > 0)    s += base[(size_t)(y-1) * WW + x];
        if (y < HH-1) s += base[(size_t)(y+1) * WW + x];
        colsum[x] = s;
    }
    __syncthreads();
    for (int x = tid; x < WW; x += 256) {
        float s = colsum[x];
        if (x > 0)    s += colsum[x-1];
        if (x < WW-1) s += colsum[x+1];
        float p = s * (1.0f/9.0f);
        g_m[n][y][x] = 1.0f / (1.0f + expf(-4.0f * (p - 0.5f)));
    }
}

// ---------------- stage 1: row DFT (35 freqs), 8 rows per block ----------------
__global__ void __launch_bounds__(256) k_rowdft() {
    __shared__ float m_s[8][WW];              // 32KB
    int yb = blockIdx.x;                      // 128 blocks of 8 rows
    int n  = blockIdx.y;
    int tid = threadIdx.x;
    #pragma unroll
    for (int yy = 0; yy < 8; yy++)
        for (int x = tid; x < WW; x += 256)
            m_s[yy][x] = g_m[n][yb*8 + yy][x];
    __syncthreads();
    int warp = tid >> 5, lane = tid & 31;     // 8 warps
    for (int j2 = warp; j2 < KD; j2 += 8) {
        int a = FC - j2;                      // freq f2 = j2-17 -> e^{-2pi i f2 x/N} = cs[(a*x) mod N]
        float2 t  = g_cs[(a * lane) & 1023];
        float2 st = g_cs[(a * 32)   & 1023];  // warp-uniform
        float ar[8], ai[8];
        #pragma unroll
        for (int yy = 0; yy < 8; yy++) { ar[yy] = 0.f; ai[yy] = 0.f; }
        for (int i = 0; i < 32; i++) {
            int x = lane + 32*i;
            #pragma unroll
            for (int yy = 0; yy < 8; yy++) {
                float mv = m_s[yy][x];
                ar[yy] += mv * t.x;
                ai[yy] += mv * t.y;
            }
            float tx = t.x*st.x - t.y*st.y;   // exact-step recurrence (32 steps)
            float ty = t.x*st.y + t.y*st.x;
            t = make_float2(tx, ty);
        }
        #pragma unroll
        for (int yy = 0; yy < 8; yy++) {
            for (int o = 16; o; o >>= 1) {
                ar[yy] += __shfl_xor_sync(0xffffffffu, ar[yy], o);
                ai[yy] += __shfl_xor_sync(0xffffffffu, ai[yy], o);
            }
        }
        if (lane == 0) {
            #pragma unroll
            for (int yy = 0; yy < 8; yy++)
                g_T[n][j2][yb*8 + yy] = make_float2(ar[yy], ai[yy]);
        }
    }
}

// ---------------- stage 2: column DFT -> 35x35 spec (coalesced) ----------------
__global__ void __launch_bounds__(128) k_coldft() {
    int j1 = blockIdx.x, j2 = blockIdx.y, n = blockIdx.z;
    int tid = threadIdx.x;
    int a = FC - j1;
    float2 t  = g_cs[(a * tid) & 1023];
    float2 st = g_cs[(a * 128) & 1023];
    float ar = 0.f, ai = 0.f;
    #pragma unroll
    for (int i = 0; i < 8; i++) {
        int y = tid + 128*i;
        float2 T = g_T[n][j2][y];             // coalesced
        ar += T.x*t.x - T.y*t.y;
        ai += T.x*t.y + T.y*t.x;
        float tx = t.x*st.x - t.y*st.y;
        float ty = t.x*st.y + t.y*st.x;
        t = make_float2(tx, ty);
    }
    for (int o = 16; o; o >>= 1) {
        ar += __shfl_xor_sync(0xffffffffu, ar, o);
        ai += __shfl_xor_sync(0xffffffffu, ai, o);
    }
    __shared__ float2 part[4];
    int warp = tid >> 5, lane = tid & 31;
    if (lane == 0) part[warp] = make_float2(ar, ai);
    __syncthreads();
    if (tid == 0) {
        float sr = 0.f, si = 0.f;
        #pragma unroll
        for (int wq = 0; wq < 4; wq++) { sr += part[wq].x; si += part[wq].y; }
        const float norm = 1.0f / (1024.0f * 1024.0f);
        g_spec[n][j1][j2] = make_float2(sr * norm, si * norm);
    }
}

// ---------------- stage 3: R[k,u,x] = sum_v (spec*kernel)[u,v] * e^{+2pi i v x/1024} ----------
// B folded in; f32x2 packed over u-pairs.
__global__ void __launch_bounds__(256) k_R(const float* __restrict__ fr, const float* __restrict__ fi,
                                           const float* __restrict__ dr, const float* __restrict__ di) {
    __shared__ float2 Bxx[KD][U2P];           // (B[2u2][v].x, B[2u2+1][v].x)
    __shared__ float2 Byy[KD][U2P];
    __shared__ float2 cs[1024];
    int xt  = blockIdx.x;                     // 4 tiles of 256 x
    int k   = blockIdx.y;
    int nbr = blockIdx.z; int n = nbr >> 1, br = nbr & 1;
    int tid = threadIdx.x;
    const float* krp = (br == 0) ? fr : dr;
    const float* kip = (br == 0) ? fi : di;
    for (int i = tid; i < KD*U2; i += 256) {
        int u2 = i / KD, v = i % KD;          // v fastest -> coalesced kernel reads
        int u0 = 2*u2, u1 = u0 + 1;
        float2 A0 = g_spec[n][u0][v];
        float Kr = krp[(k*KD + u0)*KD + v];
        float Ki = kip[(k*KD + u0)*KD + v];
        float b0x = A0.x*Kr - A0.y*Ki, b0y = A0.x*Ki + A0.y*Kr;
        float b1x = 0.f, b1y = 0.f;
        if (u1 < KD) {
            float2 A1 = g_spec[n][u1][v];
            float Kr1 = krp[(k*KD + u1)*KD + v];
            float Ki1 = kip[(k*KD + u1)*KD + v];
            b1x = A1.x*Kr1 - A1.y*Ki1; b1y = A1.x*Ki1 + A1.y*Kr1;
        }
        Bxx[v][u2] = make_float2(b0x, b1x);
        Byy[v][u2] = make_float2(b0y, b1y);
    }
    for (int i = tid; i < 1024; i += 256) cs[i] = g_cs[i];
    __syncthreads();
    int x = xt*256 + tid;
    unsigned long long aR[U2], aI[U2];
    #pragma unroll
    for (int u2 = 0; u2 < U2; u2++) { aR[u2] = 0ull; aI[u2] = 0ull; }
    for (int v = 0; v < KD; v++) {
        float2 p = cs[(v * x) & 1023];
        unsigned long long pxx = pk2(p.x,  p.x);
        unsigned long long pyy = pk2(p.y,  p.y);
        unsigned long long nyy = pk2(-p.y, -p.y);
        #pragma unroll
        for (int u2 = 0; u2 < U2; u2++) {
            unsigned long long bx = *reinterpret_cast<const unsigned long long*>(&Bxx[v][u2]);
            unsigned long long by = *reinterpret_cast<const unsigned long long*>(&Byy[v][u2]);
            aR[u2] = fma2(bx, pxx, aR[u2]);   // (b0x*px, b1x*px)
            aR[u2] = fma2(by, nyy, aR[u2]);   // -(b0y*py, b1y*py)
            aI[u2] = fma2(bx, pyy, aI[u2]);
            aI[u2] = fma2(by, pxx, aI[u2]);
        }
    }
    #pragma unroll
    for (int u2 = 0; u2 < U2; u2++) {
        float r0, r1, i0, i1;
        upk2(aR[u2], r0, r1);
        upk2(aI[u2], i0, i1);
        g_R[n][br][k][2*u2][x] = make_float2(r0, i0);
        if (2*u2 + 1 < KD) g_R[n][br][k][2*u2+1][x] = make_float2(r1, i1);
    }
}

// ---------------- stage 4a: partial Gram (f32x2 packed) ----------------
// Dpart[kg][du,x] = sum_{k in group} s_k * sum_u R[k,u,x]*conj(R[k,u-du,x])
template <int DU0, int DW>
__device__ __forceinline__ void gram_half(int n, int br, int kg, int x, const float* sp) {
    unsigned long long acc[DW];
    #pragma unroll
    for (int j = 0; j < DW; j++) acc[j] = 0ull;
    #pragma unroll 1
    for (int kk = 0; kk < 3; kk++) {
        int k = kg*3 + kk;
        float s = sp[k];
        float2 Ru[KD];
        #pragma unroll
        for (int u = 0; u < KD; u++) Ru[u] = g_R[n][br][k][u][x];
        #pragma unroll
        for (int u = 0; u < KD; u++) {
            float ax = s * Ru[u].x;
            float ay = s * Ru[u].y;
            unsigned long long axy  = pk2(ax, ay);
            unsigned long long ayxn = pk2(ay, -ax);
            #pragma unroll
            for (int j = 0; j < DW; j++) {
                if (DU0 + j <= u) {
                    float2 b = Ru[u - DU0 - j];
                    unsigned long long bxx = pk2(b.x, b.x);
                    unsigned long long byy = pk2(b.y, b.y);
                    acc[j] = fma2(axy,  bxx, acc[j]);   // (ax*bx, ay*bx)
                    acc[j] = fma2(ayxn, byy, acc[j]);   // (ay*by, -ax*by)
                }
            }
        }
    }
    #pragma unroll
    for (int j = 0; j < DW; j++) {
        float rx, ry;
        upk2(acc[j], rx, ry);
        g_Dpart[kg][n][br][DU0 + j][x] = make_float2(rx, ry);
    }
}

__global__ void __launch_bounds__(128) k_D1(const float* __restrict__ fs, const float* __restrict__ ds) {
    int xt  = blockIdx.x;                    // 8 tiles of 128 x
    int kg  = blockIdx.y;                    // 8 k-groups of 3
    int z   = blockIdx.z;                    // nbr(4) * half(2)
    int nbr = z >> 1, half = z & 1;
    int n = nbr >> 1, br = nbr & 1;
    int x = xt*128 + threadIdx.x;
    const float* sp = (br == 0) ? fs : ds;
    if (half == 0) gram_half<0, 18>(n, br, kg, x, sp);
    else           gram_half<18, 17>(n, br, kg, x, sp);
}

// ---------------- stage 4b: reduce k-group partials ----------------
__global__ void __launch_bounds__(1024) k_D2() {
    int du = blockIdx.x, nbr = blockIdx.y; int n = nbr >> 1, br = nbr & 1;
    int x = threadIdx.x;
    float sx = 0.f, sy = 0.f;
    #pragma unroll
    for (int kg = 0; kg < 8; kg++) {
        float2 t = g_Dpart[kg][n][br][du][x];
        sx += t.x; sy += t.y;
    }
    g_D[n][br][du][x] = make_float2(sx, sy);
}

// ---------------- stage 5: synthesis + outputs (focus & defocus merged) ----------------
// I(y,x) = D[0,x].re + 2 * sum_{du=1..34} Re(D[du,x] * e^{+2pi i du y/1024})
__global__ void __launch_bounds__(256) k_final(float* __restrict__ out) {
    __shared__ float2 cs[1024];
    int xs = blockIdx.x;                     // 32-wide x strip
    int yq = blockIdx.y;                     // 0..3 (256 rows each)
    int bz = blockIdx.z;                     // n(2) x br(2)
    int n = bz >> 1, br = bz & 1;
    int tid = threadIdx.x;
    for (int i = tid; i < 1024; i += 256) cs[i] = g_cs[i];
    int lane = tid & 31, warp = tid >> 5;    // 8 warps
    int x = xs*32 + lane;

    float D0 = g_D[n][br][0][x].x;           // D[0] is real
    float2 Dc[KD-1];
    #pragma unroll
    for (int du = 1; du < KD; du++) {
        float2 t = g_D[n][br][du][x];
        Dc[du-1] = make_float2(2.f*t.x, 2.f*t.y);
    }
    __syncthreads();

    const size_t plane = (size_t)NB * HH * WW;
    const size_t base  = (size_t)n * HH * WW;
    for (int yy = 0; yy < 32; yy++) {
        int y = yq*256 + warp*32 + yy;
        float I = D0;
        #pragma unroll
        for (int du = 1; du < KD; du++) {
            float2 t = cs[(du * y) & 1023];  // warp-uniform -> broadcast LDS
            I += Dc[du-1].x * t.x - Dc[du-1].y * t.y;
        }
        size_t o = base + (size_t)y * WW + x;
        if (br == 0) {
            float Imax = 1.0404f * I;        // dose 1.02^2
            out[o]           = 1.f/(1.f + expf(-50.f*(I    - 0.225f)));  // nominal
            out[2*plane + o] = 1.f/(1.f + expf(-50.f*(Imax - 0.225f)));  // outer
            out[3*plane + o] = I;                                        // x_out
            out[5*plane + o] = Imax;                                     // x_out_max
        } else {
            float Imin = 0.9604f * I;        // dose 0.98^2
            out[plane   + o] = 1.f/(1.f + expf(-50.f*(Imin - 0.225f)));  // inner
            out[4*plane + o] = Imin;                                     // x_out_min
        }
    }
}

// ---------------- launch ----------------
extern "C" void kernel_launch(void* const* d_in, const int* in_sizes, int n_in,
                              void* d_out, int out_size) {
    const float* mask = (const float*)d_in[0];
    const float* fr   = (const float*)d_in[1];
    const float* fi   = (const float*)d_in[2];
    const float* dr   = (const float*)d_in[3];
    const float* di   = (const float*)d_in[4];
    const float* fs   = (const float*)d_in[5];
    const float* ds   = (const float*)d_in[6];
    float* out = (float*)d_out;

    k_table  <<<1, 1024>>>();
    k_mask   <<<dim3(1024, NB), 256>>>(mask);
    k_rowdft <<<dim3(128, NB), 256>>>();
    k_coldft <<<dim3(KD, KD, NB), 128>>>();
    k_R      <<<dim3(4, KK, 4), 256>>>(fr, fi, dr, di);
    k_D1     <<<dim3(8, 8, 8), 128>>>(fs, ds);
    k_D2     <<<dim3(KD, 4), 1024>>>();
    k_final  <<<dim3(32, 4, 4), 256>>>(out);
}

// round 5
// speedup vs baseline: 1.6795x; 1.1410x over previous
#include <cuda_runtime.h>
#include <math.h>

#define HH 1024
#define WW 1024
#define NB 2
#define KK 24   // number of SOCS kernels
#define KD 35   // kernel spatial size / cropped spectrum size
#define FC 17   // center offset: frequency f = index - 17
#define U2 18   // ceil(KD/2) u-pairs
#define U2P 20  // padded row length for LDS.128

// ---------------- scratch (static __device__, no allocation) ----------------
__device__ float2 g_cs[1024];                 // e^{+2pi i t/1024}
__device__ float2 g_T[NB][KD][HH];            // row DFT, transposed (j2-major)
__device__ float2 g_spec[NB][KD][KD];         // cropped spectrum (1/(H*W) folded)
__device__ float2 g_R[NB][2][KK][KD][WW];     // row-synthesized fields
__device__ float2 g_Dpart[8][NB][2][KD][WW];  // per-k-group partial Gram
__device__ float2 g_D[NB][2][KD][WW];         // cross-spectral density over du

// ---------------- f32x2 packed helpers (Blackwell) ----------------
__device__ __forceinline__ unsigned long long pk2(float lo, float hi) {
    unsigned long long r;
    asm("mov.b64 %0, {%1, %2};" : "=l"(r) : "f"(lo), "f"(hi));
    return r;
}
__device__ __forceinline__ unsigned long long fma2(unsigned long long a, unsigned long long b, unsigned long long c) {
    unsigned long long d;
    asm("fma.rn.f32x2 %0, %1, %2, %3;" : "=l"(d) : "l"(a), "l"(b), "l"(c));
    return d;
}
__device__ __forceinline__ void upk2(unsigned long long v, float& lo, float& hi) {
    asm("mov.b64 {%0, %1}, %2;" : "=f"(lo), "=f"(hi) : "l"(v));
}

// ---------------- twiddle table ----------------
__global__ void k_table() {
    int t = threadIdx.x;
    float s, c;
    sincospif((float)t / 512.0f, &s, &c);     // angle = 2*pi*t/1024
    g_cs[t] = make_float2(c, s);
}

// ---------------- stage 1: fused avepool3+sigmoid + row DFT, 4 rows/block ----------------
__global__ void __launch_bounds__(256) k_rowdft(const float* __restrict__ mask) {
    __shared__ float raw[6][WW];              // rows yb*4-1 .. yb*4+4
    __shared__ float m_s[4][WW];              // pooled+sigmoid rows
    int yb = blockIdx.x;                      // 256 blocks of 4 rows
    int n  = blockIdx.y;
    int tid = threadIdx.x;
    const float* base = mask + (size_t)n * HH * WW;
    #pragma unroll
    for (int j = 0; j < 6; j++) {
        int gy = yb*4 - 1 + j;
        for (int x = tid; x < WW; x += 256)
            raw[j][x] = (gy >= 0 && gy < HH) ? base[(size_t)gy * WW + x] : 0.f;
    }
    __syncthreads();
    // vertical sums in place (column-local, no race)
    for (int x = tid; x < WW; x += 256) {
        float r0 = raw[0][x], r1 = raw[1][x], r2 = raw[2][x];
        float r3 = raw[3][x], r4 = raw[4][x], r5 = raw[5][x];
        raw[0][x] = r0 + r1 + r2;
        raw[1][x] = r1 + r2 + r3;
        raw[2][x] = r2 + r3 + r4;
        raw[3][x] = r3 + r4 + r5;
    }
    __syncthreads();
    // horizontal + sigmoid
    for (int x = tid; x < WW; x += 256) {
        #pragma unroll
        for (int yy = 0; yy < 4; yy++) {
            float s = raw[yy][x];
            if (x > 0)    s += raw[yy][x-1];
            if (x < WW-1) s += raw[yy][x+1];
            float p = s * (1.0f/9.0f);
            m_s[yy][x] = 1.0f / (1.0f + expf(-4.0f * (p - 0.5f)));
        }
    }
    __syncthreads();
    // row DFT: 35 freqs over 8 warps, packed (ar,ai) accumulators
    int warp = tid >> 5, lane = tid & 31;
    for (int j2 = warp; j2 < KD; j2 += 8) {
        int a = FC - j2;                      // e^{-2pi i (j2-17) x/N} = cs[(a*x) mod N]
        float2 t  = g_cs[(a * lane) & 1023];
        float2 st = g_cs[(a * 32)   & 1023];  // warp-uniform step
        unsigned long long acc[4] = {0ull, 0ull, 0ull, 0ull};
        for (int i = 0; i < 32; i++) {
            int x = lane + 32*i;
            unsigned long long t2 = pk2(t.x, t.y);
            #pragma unroll
            for (int yy = 0; yy < 4; yy++) {
                float mv = m_s[yy][x];
                acc[yy] = fma2(pk2(mv, mv), t2, acc[yy]);
            }
            float tx = t.x*st.x - t.y*st.y;   // exact-step recurrence
            float ty = t.x*st.y + t.y*st.x;
            t = make_float2(tx, ty);
        }
        #pragma unroll
        for (int yy = 0; yy < 4; yy++) {
            float ar, ai;
            upk2(acc[yy], ar, ai);
            for (int o = 16; o; o >>= 1) {
                ar += __shfl_xor_sync(0xffffffffu, ar, o);
                ai += __shfl_xor_sync(0xffffffffu, ai, o);
            }
            if (lane == 0) g_T[n][j2][yb*4 + yy] = make_float2(ar, ai);
        }
    }
}

// ---------------- stage 2: column DFT, one block per (j2,n), g_T read once ----------------
__global__ void __launch_bounds__(256) k_coldft() {
    __shared__ float2 Ts[HH];                 // 8KB
    int j2 = blockIdx.x, n = blockIdx.y;
    int tid = threadIdx.x;
    for (int i = tid; i < HH; i += 256) Ts[i] = g_T[n][j2][i];
    __syncthreads();
    int warp = tid >> 5, lane = tid & 31;     // 8 warps
    const float norm = 1.0f / (1024.0f * 1024.0f);
    for (int j1 = warp; j1 < KD; j1 += 8) {
        int a = FC - j1;
        float2 t  = g_cs[(a * lane) & 1023];
        float2 st = g_cs[(a * 32)   & 1023];
        float ar = 0.f, ai = 0.f;
        for (int i = 0; i < 32; i++) {
            float2 T = Ts[lane + 32*i];
            ar += T.x*t.x - T.y*t.y;
            ai += T.x*t.y + T.y*t.x;
            float tx = t.x*st.x - t.y*st.y;
            float ty = t.x*st.y + t.y*st.x;
            t = make_float2(tx, ty);
        }
        for (int o = 16; o; o >>= 1) {
            ar += __shfl_xor_sync(0xffffffffu, ar, o);
            ai += __shfl_xor_sync(0xffffffffu, ai, o);
        }
        if (lane == 0) g_spec[n][j1][j2] = make_float2(ar * norm, ai * norm);
    }
}

// ---------------- stage 3: R[k,u,x] = sum_v (spec*kernel)[u,v] * e^{+2pi i v x/1024} ----------
__global__ void __launch_bounds__(256) k_R(const float* __restrict__ fr, const float* __restrict__ fi,
                                           const float* __restrict__ dr, const float* __restrict__ di) {
    __shared__ float2 Bxx[KD][U2P];           // (B[2u2][v].x, B[2u2+1][v].x)
    __shared__ float2 Byy[KD][U2P];
    __shared__ float2 cs[1024];
    int xt  = blockIdx.x;                     // 4 tiles of 256 x
    int k   = blockIdx.y;
    int nbr = blockIdx.z; int n = nbr >> 1, br = nbr & 1;
    int tid = threadIdx.x;
    const float* krp = (br == 0) ? fr : dr;
    const float* kip = (br == 0) ? fi : di;
    for (int i = tid; i < KD*U2; i += 256) {
        int u2 = i / KD, v = i % KD;
        int u0 = 2*u2, u1 = u0 + 1;
        float2 A0 = g_spec[n][u0][v];
        float Kr = krp[(k*KD + u0)*KD + v];
        float Ki = kip[(k*KD + u0)*KD + v];
        float b0x = A0.x*Kr - A0.y*Ki, b0y = A0.x*Ki + A0.y*Kr;
        float b1x = 0.f, b1y = 0.f;
        if (u1 < KD) {
            float2 A1 = g_spec[n][u1][v];
            float Kr1 = krp[(k*KD + u1)*KD + v];
            float Ki1 = kip[(k*KD + u1)*KD + v];
            b1x = A1.x*Kr1 - A1.y*Ki1; b1y = A1.x*Ki1 + A1.y*Kr1;
        }
        Bxx[v][u2] = make_float2(b0x, b1x);
        Byy[v][u2] = make_float2(b0y, b1y);
    }
    for (int i = tid; i < 1024; i += 256) cs[i] = g_cs[i];
    __syncthreads();
    int x = xt*256 + tid;
    unsigned long long aR[U2], aI[U2];
    #pragma unroll
    for (int u2 = 0; u2 < U2; u2++) { aR[u2] = 0ull; aI[u2] = 0ull; }
    for (int v = 0; v < KD; v++) {
        float2 p = cs[(v * x) & 1023];
        unsigned long long pxx = pk2(p.x,  p.x);
        unsigned long long pyy = pk2(p.y,  p.y);
        unsigned long long nyy = pk2(-p.y, -p.y);
        #pragma unroll
        for (int u2 = 0; u2 < U2; u2++) {
            unsigned long long bx = *reinterpret_cast<const unsigned long long*>(&Bxx[v][u2]);
            unsigned long long by = *reinterpret_cast<const unsigned long long*>(&Byy[v][u2]);
            aR[u2] = fma2(bx, pxx, aR[u2]);
            aR[u2] = fma2(by, nyy, aR[u2]);
            aI[u2] = fma2(bx, pyy, aI[u2]);
            aI[u2] = fma2(by, pxx, aI[u2]);
        }
    }
    #pragma unroll
    for (int u2 = 0; u2 < U2; u2++) {
        float r0, r1, i0, i1;
        upk2(aR[u2], r0, r1);
        upk2(aI[u2], i0, i1);
        g_R[n][br][k][2*u2][x] = make_float2(r0, i0);
        if (2*u2 + 1 < KD) g_R[n][br][k][2*u2+1][x] = make_float2(r1, i1);
    }
}

// ---------------- stage 4a: partial Gram (f32x2 packed) ----------------
template <int DU0, int DW>
__device__ __forceinline__ void gram_half(int n, int br, int kg, int x, const float* sp) {
    unsigned long long acc[DW];
    #pragma unroll
    for (int j = 0; j < DW; j++) acc[j] = 0ull;
    #pragma unroll 1
    for (int kk = 0; kk < 3; kk++) {
        int k = kg*3 + kk;
        float s = sp[k];
        float2 Ru[KD];
        #pragma unroll
        for (int u = 0; u < KD; u++) Ru[u] = g_R[n][br][k][u][x];
        #pragma unroll
        for (int u = 0; u < KD; u++) {
            float ax = s * Ru[u].x;
            float ay = s * Ru[u].y;
            unsigned long long axy  = pk2(ax, ay);
            unsigned long long ayxn = pk2(ay, -ax);
            #pragma unroll
            for (int j = 0; j < DW; j++) {
                if (DU0 + j <= u) {
                    float2 b = Ru[u - DU0 - j];
                    acc[j] = fma2(axy,  pk2(b.x, b.x), acc[j]);
                    acc[j] = fma2(ayxn, pk2(b.y, b.y), acc[j]);
                }
            }
        }
    }
    #pragma unroll
    for (int j = 0; j < DW; j++) {
        float rx, ry;
        upk2(acc[j], rx, ry);
        g_Dpart[kg][n][br][DU0 + j][x] = make_float2(rx, ry);
    }
}

__global__ void __launch_bounds__(128) k_D1(const float* __restrict__ fs, const float* __restrict__ ds) {
    int xt  = blockIdx.x;                    // 8 tiles of 128 x
    int kg  = blockIdx.y;                    // 8 k-groups of 3
    int z   = blockIdx.z;                    // nbr(4) * half(2)
    int nbr = z >> 1, half = z & 1;
    int n = nbr >> 1, br = nbr & 1;
    int x = xt*128 + threadIdx.x;
    const float* sp = (br == 0) ? fs : ds;
    if (half == 0) gram_half<0, 18>(n, br, kg, x, sp);
    else           gram_half<18, 17>(n, br, kg, x, sp);
}

// ---------------- stage 4b: reduce k-group partials ----------------
__global__ void __launch_bounds__(1024) k_D2() {
    int du = blockIdx.x, nbr = blockIdx.y; int n = nbr >> 1, br = nbr & 1;
    int x = threadIdx.x;
    float sx = 0.f, sy = 0.f;
    #pragma unroll
    for (int kg = 0; kg < 8; kg++) {
        float2 t = g_Dpart[kg][n][br][du][x];
        sx += t.x; sy += t.y;
    }
    g_D[n][br][du][x] = make_float2(sx, sy);
}

// ---------------- stage 5: synthesis (du-pair packed) + outputs ----------------
// I(y,x) = D[0,x].re + sum_p [2D[2p+1].x * c(2p+1,y) - 2D[2p+1].y * s(2p+1,y) + same for 2p+2]
__global__ void __launch_bounds__(256) k_final(float* __restrict__ out) {
    __shared__ unsigned long long twx[128][17];   // (cos(du0*y), cos(du1*y)) per pair
    __shared__ unsigned long long twy[128][17];   // (sin(du0*y), sin(du1*y))
    int xs = blockIdx.x;                     // 32-wide x strip
    int yq = blockIdx.y;                     // 0..7 (128 rows each)
    int bz = blockIdx.z;                     // n(2) x br(2)
    int n = bz >> 1, br = bz & 1;
    int tid = threadIdx.x;
    // prepass: packed twiddles for this block's 128 rows
    for (int idx = tid; idx < 128*17; idx += 256) {
        int yp = idx / 17, p = idx % 17;
        int y = yq*128 + yp;
        float2 c0 = g_cs[((2*p+1) * y) & 1023];
        float2 c1 = g_cs[((2*p+2) * y) & 1023];
        twx[yp][p] = pk2(c0.x, c1.x);
        twy[yp][p] = pk2(c0.y, c1.y);
    }
    int lane = tid & 31, warp = tid >> 5;    // 8 warps x 16 y each
    int x = xs*32 + lane;
    float D0 = g_D[n][br][0][x].x;           // D[0] is real
    unsigned long long dcx2[17], dcy2[17];
    #pragma unroll
    for (int p = 0; p < 17; p++) {
        float2 t0 = g_D[n][br][2*p+1][x];
        float2 t1 = g_D[n][br][2*p+2][x];
        dcx2[p] = pk2( 2.f*t0.x,  2.f*t1.x);
        dcy2[p] = pk2(-2.f*t0.y, -2.f*t1.y);
    }
    __syncthreads();

    const size_t plane = (size_t)NB * HH * WW;
    const size_t base  = (size_t)n * HH * WW;
    for (int yy = 0; yy < 16; yy++) {
        int yp = warp*16 + yy;
        int y  = yq*128 + yp;
        unsigned long long acc = pk2(D0, 0.f);
        #pragma unroll
        for (int p = 0; p < 17; p++) {
            acc = fma2(dcx2[p], twx[yp][p], acc);
            acc = fma2(dcy2[p], twy[yp][p], acc);
        }
        float Ia, Ib;
        upk2(acc, Ia, Ib);
        float I = Ia + Ib;
        size_t o = base + (size_t)y * WW + x;
        if (br == 0) {
            float Imax = 1.0404f * I;        // dose 1.02^2
            out[o]           = 1.f/(1.f + expf(-50.f*(I    - 0.225f)));  // nominal
            out[2*plane + o] = 1.f/(1.f + expf(-50.f*(Imax - 0.225f)));  // outer
            out[3*plane + o] = I;                                        // x_out
            out[5*plane + o] = Imax;                                     // x_out_max
        } else {
            float Imin = 0.9604f * I;        // dose 0.98^2
            out[plane   + o] = 1.f/(1.f + expf(-50.f*(Imin - 0.225f)));  // inner
            out[4*plane + o] = Imin;                                     // x_out_min
        }
    }
}

// ---------------- launch ----------------
extern "C" void kernel_launch(void* const* d_in, const int* in_sizes, int n_in,
                              void* d_out, int out_size) {
    const float* mask = (const float*)d_in[0];
    const float* fr   = (const float*)d_in[1];
    const float* fi   = (const float*)d_in[2];
    const float* dr   = (const float*)d_in[3];
    const float* di   = (const float*)d_in[4];
    const float* fs   = (const float*)d_in[5];
    const float* ds   = (const float*)d_in[6];
    float* out = (float*)d_out;

    k_table  <<<1, 1024>>>();
    k_rowdft <<<dim3(256, NB), 256>>>(mask);
    k_coldft <<<dim3(KD, NB), 256>>>();
    k_R      <<<dim3(4, KK, 4), 256>>>(fr, fi, dr, di);
    k_D1     <<<dim3(8, 8, 8), 128>>>(fs, ds);
    k_D2     <<<dim3(KD, 4), 1024>>>();
    k_final  <<<dim3(32, 8, 4), 256>>>(out);
}